// round 13
// baseline (speedup 1.0000x reference)
#include <cuda_runtime.h>
#include <math.h>

#define NN   100000
#define EE   1600000
#define FIN  128
#define HID  64
#define NC   40
#define CAP  64                    // padded CSR slots per node (P[deg>64] ~ 1e-19)
#define NB1  ((NN + 255) / 256)
#define WN   (HID * 128 + HID * 64 + NC)   // 12328 weight-fold work items

typedef unsigned long long u64;

// ---------------- f32x2 packed-FMA helpers (Blackwell FFMA2) ----------------
__device__ __forceinline__ u64 dup2(float v) {
    u64 r; asm("mov.b64 %0,{%1,%1};" : "=l"(r) : "f"(v)); return r;
}
__device__ __forceinline__ u64 fma2(u64 a, u64 b, u64 c) {
    u64 d; asm("fma.rn.f32x2 %0,%1,%2,%3;" : "=l"(d) : "l"(a), "l"(b), "l"(c)); return d;
}
__device__ __forceinline__ float2 upk2(u64 v) {
    float lo, hi; asm("mov.b64 {%0,%1},%2;" : "=f"(lo), "=f"(hi) : "l"(v));
    return make_float2(lo, hi);
}

// ---------------- device scratch ----------------
__device__ int   g_is64;
__device__ int   g_cnt[NN];
__device__ int   g_esrc[(size_t)NN * CAP];       // padded CSR: src per slot
__device__ float g_dinv[NN];
__device__ __align__(16) float g_h0[NN * HID];   // x @ conv0_w ; later reused as hB
__device__ __align__(16) float g_hA[NN * HID];   // agg layer-0 output (elu'd)
__device__ __align__(16) float g_t1[NN * HID];   // hA @ conv1_w
__device__ __align__(16) float g_p0[NN * NC];    // hA @ F0
__device__ __align__(16) float g_Wc[HID * 128];  // packed [conv1_w | F0 | 0]  (64x128)
__device__ __align__(16) float g_Wd[HID * 64];   // packed [F1 | 0]            (64x64)
__device__ float g_bf[NC];

__device__ __forceinline__ float elu1(float v) { return v > 0.0f ? v : expm1f(v); }

__device__ __forceinline__ int edge_at(const int* __restrict__ ei32, long long idx) {
    return g_is64 ? ei32[idx * 2] : ei32[idx];
}

// ---------------- zero counters + dtype detect (block 0) ----------------
__global__ void k_zero(const int* __restrict__ ei32) {
    int i = blockIdx.x * blockDim.x + threadIdx.x;
    if (i < NN) g_cnt[i] = 0;
    if (blockIdx.x == 0) {
        __shared__ int nz;
        if (threadIdx.x == 0) nz = 0;
        __syncthreads();
        if (ei32[threadIdx.x * 2 + 1] != 0) atomicAdd(&nz, 1);
        __syncthreads();
        if (threadIdx.x == 0) g_is64 = (nz == 0) ? 1 : 0;
    }
}

// ---------------- single-pass fill: slot = atomic cursor on g_cnt ----------------
__global__ void k_fill(const int* __restrict__ ei32) {
    int e = blockIdx.x * blockDim.x + threadIdx.x;
    if (e < EE) {
        int s = edge_at(ei32, e);
        int d = edge_at(ei32, (long long)EE + e);
        if (s >= 0 && s < NN && d >= 0 && d < NN) {
            int c = atomicAdd(&g_cnt[d], 1);
            if (c < CAP) g_esrc[(size_t)d * CAP + c] = s;
        }
    }
}

// ---------------- fold weights (blocks 0..48) + dinv (rest) ----------------
// work items: [0, WN) = weight fold ; [WN, WN+NN) = dinv
__global__ __launch_bounds__(256) void k_fusew(
        const float* __restrict__ lin0_w, const float* __restrict__ lin0_b,
        const float* __restrict__ lin1_w, const float* __restrict__ lin1_b,
        const float* __restrict__ out_w,  const float* __restrict__ out_b,
        const float* __restrict__ conv1_w) {
    int i = blockIdx.x * blockDim.x + threadIdx.x;

    if (blockIdx.x * 256 >= WN) {        // pure-dinv block: no staging
        int node = i - WN;
        if (node < NN) g_dinv[node] = rsqrtf((float)g_cnt[node] + 1.0f);
        return;
    }

    __shared__ float ow[2 * HID * NC];   // full out_w staged (20KB)
    for (int t = threadIdx.x; t < 2 * HID * NC; t += 256) ow[t] = out_w[t];
    __syncthreads();

    if (i < HID * 128) {                         // g_Wc
        int k = i >> 7, cc = i & 127;
        float v = 0.0f;
        if (cc < 64) {
            v = conv1_w[k * HID + cc];
        } else if (cc < 104) {
            int c = cc - 64;
            float s = 0.0f;
            #pragma unroll 8
            for (int m = 0; m < HID; m++) s += __ldg(&lin0_w[k * HID + m]) * ow[m * NC + c];
            v = s;
        }
        g_Wc[i] = v;
    } else if (i < HID * 128 + HID * 64) {       // g_Wd
        int jj = i - HID * 128;
        int k = jj >> 6, cc = jj & 63;
        float v = 0.0f;
        if (cc < NC) {
            float s = 0.0f;
            #pragma unroll 8
            for (int m = 0; m < HID; m++) s += __ldg(&lin1_w[k * HID + m]) * ow[(HID + m) * NC + cc];
            v = s;
        }
        g_Wd[jj] = v;
    } else if (i < WN) {                         // g_bf
        int c = i - HID * 128 - HID * 64;
        float s = out_b[c];
        for (int m = 0; m < HID; m++)
            s += lin0_b[m] * ow[m * NC + c] + lin1_b[m] * ow[(HID + m) * NC + c];
        g_bf[c] = s;
    } else {                                     // straddle block tail: dinv
        int node = i - WN;
        if (node < NN) g_dinv[node] = rsqrtf((float)g_cnt[node] + 1.0f);
    }
}

// ---------------- GEMM0: h0 = x @ conv0_w   BM128 BN64 BK32, f32x2, x-prefetch pipeline ----------------
__global__ __launch_bounds__(256, 3) void k_gemm0(const float* __restrict__ x,
                                                  const float* __restrict__ w) {
    __shared__ float As[32][132];   // k-major
    __shared__ float Ws[32][64];
    const int tid = threadIdx.x;
    const int row0 = blockIdx.x * 128;
    const int tx = tid & 15, ty = tid >> 4;
    const int lrow = tid & 127, lkc = tid >> 7;
    const int row = row0 + lrow;
    u64 acc2[4][4] = {};

    // prologue: prefetch tile 0 of x
    float4 pre[4];
    #pragma unroll
    for (int p = 0; p < 4; p++) {
        int kk = lkc * 16 + p * 4;
        pre[p] = (row < NN) ? *(const float4*)&x[(size_t)row * FIN + kk]
                            : make_float4(0, 0, 0, 0);
    }

    #pragma unroll
    for (int t = 0; t < 4; t++) {
        const int k0 = t * 32;
        #pragma unroll
        for (int p = 0; p < 4; p++) {
            int kk = lkc * 16 + p * 4;
            As[kk + 0][lrow] = pre[p].x; As[kk + 1][lrow] = pre[p].y;
            As[kk + 2][lrow] = pre[p].z; As[kk + 3][lrow] = pre[p].w;
        }
        #pragma unroll
        for (int r = 0; r < 2; r++) {
            int fi = tid + r * 256;
            int k = fi >> 4, c4 = (fi & 15) * 4;
            *(float4*)&Ws[k][c4] = *(const float4*)&w[(k0 + k) * HID + c4];
        }
        __syncthreads();
        if (t < 3) {
            #pragma unroll
            for (int p = 0; p < 4; p++) {
                int kk = (t + 1) * 32 + lkc * 16 + p * 4;
                pre[p] = (row < NN) ? *(const float4*)&x[(size_t)row * FIN + kk]
                                    : make_float4(0, 0, 0, 0);
            }
        }
        #pragma unroll
        for (int k = 0; k < 32; k++) {
            union { float4 f4; u64 d[2]; } ua0, ua1;
            ua0.f4 = *(const float4*)&As[k][ty * 8];
            ua1.f4 = *(const float4*)&As[k][ty * 8 + 4];
            u64 a0 = ua0.d[0], a1 = ua0.d[1], a2 = ua1.d[0], a3 = ua1.d[1];
            float4 b = *(const float4*)&Ws[k][tx * 4];
            u64 b0 = dup2(b.x), b1 = dup2(b.y), b2 = dup2(b.z), b3 = dup2(b.w);
            acc2[0][0] = fma2(a0, b0, acc2[0][0]); acc2[0][1] = fma2(a0, b1, acc2[0][1]);
            acc2[0][2] = fma2(a0, b2, acc2[0][2]); acc2[0][3] = fma2(a0, b3, acc2[0][3]);
            acc2[1][0] = fma2(a1, b0, acc2[1][0]); acc2[1][1] = fma2(a1, b1, acc2[1][1]);
            acc2[1][2] = fma2(a1, b2, acc2[1][2]); acc2[1][3] = fma2(a1, b3, acc2[1][3]);
            acc2[2][0] = fma2(a2, b0, acc2[2][0]); acc2[2][1] = fma2(a2, b1, acc2[2][1]);
            acc2[2][2] = fma2(a2, b2, acc2[2][2]); acc2[2][3] = fma2(a2, b3, acc2[2][3]);
            acc2[3][0] = fma2(a3, b0, acc2[3][0]); acc2[3][1] = fma2(a3, b1, acc2[3][1]);
            acc2[3][2] = fma2(a3, b2, acc2[3][2]); acc2[3][3] = fma2(a3, b3, acc2[3][3]);
        }
        __syncthreads();
    }
    #pragma unroll
    for (int i = 0; i < 4; i++) {
        float2 c0 = upk2(acc2[i][0]), c1 = upk2(acc2[i][1]);
        float2 c2 = upk2(acc2[i][2]), c3 = upk2(acc2[i][3]);
        int orow = row0 + ty * 8 + 2 * i;
        if (orow < NN)
            *(float4*)&g_h0[(size_t)orow * HID + tx * 4] = make_float4(c0.x, c1.x, c2.x, c3.x);
        if (orow + 1 < NN)
            *(float4*)&g_h0[(size_t)(orow + 1) * HID + tx * 4] = make_float4(c0.y, c1.y, c2.y, c3.y);
    }
}

// ---------------- gather-aggregate: lane-parallel index preload + shfl broadcast ----------------
__global__ __launch_bounds__(256) void k_agg(int layer, const float* __restrict__ bias) {
    const float2* feat = (layer == 0) ? (const float2*)g_h0 : (const float2*)g_t1;
    float2*       outh = (layer == 0) ? (float2*)g_hA      : (float2*)g_h0;
    int warp = threadIdx.x >> 5;
    int lane = threadIdx.x & 31;
    int node = blockIdx.x * 8 + warp;
    if (node >= NN) return;

    const int* el = &g_esrc[(size_t)node * CAP];
    int cnt = g_cnt[node];
    if (cnt > CAP) cnt = CAP;
    float dd = g_dinv[node];
    float2 acc = make_float2(0.0f, 0.0f);

    // lane-parallel: one coalesced pass loads all indices + coefficients
    int   s0 = 0;
    float c0 = 0.0f;
    if (lane < cnt) {
        s0 = __ldg(&el[lane]);
        c0 = dd * __ldg(&g_dinv[s0]);
    }
    int n1 = (cnt < 32) ? cnt : 32;
    #pragma unroll 4
    for (int j = 0; j < n1; j++) {
        int   s = __shfl_sync(0xffffffffu, s0, j);
        float c = __shfl_sync(0xffffffffu, c0, j);
        float2 v = __ldg(&feat[(size_t)s * 32 + lane]);
        acc.x = fmaf(c, v.x, acc.x);
        acc.y = fmaf(c, v.y, acc.y);
    }
    if (cnt > 32) {                 // rare tail (P ~ 1e-4)
        int   s1 = 0;
        float c1 = 0.0f;
        if (32 + lane < cnt) {
            s1 = __ldg(&el[32 + lane]);
            c1 = dd * __ldg(&g_dinv[s1]);
        }
        int n2 = cnt - 32;
        for (int j = 0; j < n2; j++) {
            int   s = __shfl_sync(0xffffffffu, s1, j);
            float c = __shfl_sync(0xffffffffu, c1, j);
            float2 v = __ldg(&feat[(size_t)s * 32 + lane]);
            acc.x = fmaf(c, v.x, acc.x);
            acc.y = fmaf(c, v.y, acc.y);
        }
    }
    {   // self-loop
        float2 v = __ldg(&feat[(size_t)node * 32 + lane]);
        float c = dd * dd;
        acc.x = fmaf(c, v.x, acc.x);
        acc.y = fmaf(c, v.y, acc.y);
    }
    float2 bb = __ldg(&((const float2*)bias)[lane]);
    outh[(size_t)node * 32 + lane] = make_float2(elu1(acc.x + bb.x), elu1(acc.y + bb.y));
}

// ---------------- post0: [t1|p0] = hA @ g_Wc   BM128 BN128 BK32, f32x2 ----------------
__global__ __launch_bounds__(256, 2) void k_post0() {
    __shared__ float As[32][132];
    __shared__ float Ws[32][128];
    const int tid = threadIdx.x;
    const int row0 = blockIdx.x * 128;
    const int tx = tid & 15, ty = tid >> 4;
    const int lrow = tid & 127, lkc = tid >> 7;
    u64 accL[4][4] = {}, accR[4][4] = {};

    for (int k0 = 0; k0 < HID; k0 += 32) {
        #pragma unroll
        for (int p = 0; p < 4; p++) {
            int kk = lkc * 16 + p * 4;
            int row = row0 + lrow;
            float4 v = (row < NN) ? *(const float4*)&g_hA[(size_t)row * HID + k0 + kk]
                                  : make_float4(0, 0, 0, 0);
            As[kk + 0][lrow] = v.x; As[kk + 1][lrow] = v.y;
            As[kk + 2][lrow] = v.z; As[kk + 3][lrow] = v.w;
        }
        #pragma unroll
        for (int r = 0; r < 4; r++) {
            int fi = tid + r * 256;
            int k = fi >> 5, c4 = (fi & 31) * 4;
            *(float4*)&Ws[k][c4] = *(const float4*)&g_Wc[(k0 + k) * 128 + c4];
        }
        __syncthreads();
        #pragma unroll
        for (int k = 0; k < 32; k++) {
            union { float4 f4; u64 d[2]; } ua0, ua1;
            ua0.f4 = *(const float4*)&As[k][ty * 8];
            ua1.f4 = *(const float4*)&As[k][ty * 8 + 4];
            u64 a0 = ua0.d[0], a1 = ua0.d[1], a2 = ua1.d[0], a3 = ua1.d[1];
            float4 bl = *(const float4*)&Ws[k][tx * 4];
            float4 br = *(const float4*)&Ws[k][64 + tx * 4];
            u64 l0 = dup2(bl.x), l1 = dup2(bl.y), l2 = dup2(bl.z), l3 = dup2(bl.w);
            u64 r0 = dup2(br.x), r1 = dup2(br.y), r2 = dup2(br.z), r3 = dup2(br.w);
            accL[0][0] = fma2(a0, l0, accL[0][0]); accL[0][1] = fma2(a0, l1, accL[0][1]);
            accL[0][2] = fma2(a0, l2, accL[0][2]); accL[0][3] = fma2(a0, l3, accL[0][3]);
            accL[1][0] = fma2(a1, l0, accL[1][0]); accL[1][1] = fma2(a1, l1, accL[1][1]);
            accL[1][2] = fma2(a1, l2, accL[1][2]); accL[1][3] = fma2(a1, l3, accL[1][3]);
            accL[2][0] = fma2(a2, l0, accL[2][0]); accL[2][1] = fma2(a2, l1, accL[2][1]);
            accL[2][2] = fma2(a2, l2, accL[2][2]); accL[2][3] = fma2(a2, l3, accL[2][3]);
            accL[3][0] = fma2(a3, l0, accL[3][0]); accL[3][1] = fma2(a3, l1, accL[3][1]);
            accL[3][2] = fma2(a3, l2, accL[3][2]); accL[3][3] = fma2(a3, l3, accL[3][3]);
            accR[0][0] = fma2(a0, r0, accR[0][0]); accR[0][1] = fma2(a0, r1, accR[0][1]);
            accR[0][2] = fma2(a0, r2, accR[0][2]); accR[0][3] = fma2(a0, r3, accR[0][3]);
            accR[1][0] = fma2(a1, r0, accR[1][0]); accR[1][1] = fma2(a1, r1, accR[1][1]);
            accR[1][2] = fma2(a1, r2, accR[1][2]); accR[1][3] = fma2(a1, r3, accR[1][3]);
            accR[2][0] = fma2(a2, r0, accR[2][0]); accR[2][1] = fma2(a2, r1, accR[2][1]);
            accR[2][2] = fma2(a2, r2, accR[2][2]); accR[2][3] = fma2(a2, r3, accR[2][3]);
            accR[3][0] = fma2(a3, r0, accR[3][0]); accR[3][1] = fma2(a3, r1, accR[3][1]);
            accR[3][2] = fma2(a3, r2, accR[3][2]); accR[3][3] = fma2(a3, r3, accR[3][3]);
        }
        __syncthreads();
    }
    #pragma unroll
    for (int i = 0; i < 4; i++) {
        float2 l0 = upk2(accL[i][0]), l1 = upk2(accL[i][1]);
        float2 l2 = upk2(accL[i][2]), l3 = upk2(accL[i][3]);
        float2 r0 = upk2(accR[i][0]), r1 = upk2(accR[i][1]);
        float2 r2 = upk2(accR[i][2]), r3 = upk2(accR[i][3]);
        int row = row0 + ty * 8 + 2 * i;
        if (row < NN) {
            *(float4*)&g_t1[(size_t)row * HID + tx * 4] = make_float4(l0.x, l1.x, l2.x, l3.x);
            if (tx < 10)
                *(float4*)&g_p0[(size_t)row * NC + tx * 4] = make_float4(r0.x, r1.x, r2.x, r3.x);
        }
        if (row + 1 < NN) {
            *(float4*)&g_t1[(size_t)(row + 1) * HID + tx * 4] = make_float4(l0.y, l1.y, l2.y, l3.y);
            if (tx < 10)
                *(float4*)&g_p0[(size_t)(row + 1) * NC + tx * 4] = make_float4(r0.y, r1.y, r2.y, r3.y);
        }
    }
}

// ---------------- post1: out = p0 + hB @ g_Wd + bf   BM128 BN64 BK32, f32x2 ----------------
__global__ __launch_bounds__(256) void k_post1(float* __restrict__ out) {
    __shared__ float As[32][132];
    __shared__ float Ws[32][64];
    const int tid = threadIdx.x;
    const int row0 = blockIdx.x * 128;
    const int tx = tid & 15, ty = tid >> 4;
    const int lrow = tid & 127, lkc = tid >> 7;
    u64 acc2[4][4] = {};

    for (int k0 = 0; k0 < HID; k0 += 32) {
        #pragma unroll
        for (int p = 0; p < 4; p++) {
            int kk = lkc * 16 + p * 4;
            int row = row0 + lrow;
            float4 v = (row < NN) ? *(const float4*)&g_h0[(size_t)row * HID + k0 + kk]
                                  : make_float4(0, 0, 0, 0);
            As[kk + 0][lrow] = v.x; As[kk + 1][lrow] = v.y;
            As[kk + 2][lrow] = v.z; As[kk + 3][lrow] = v.w;
        }
        #pragma unroll
        for (int r = 0; r < 2; r++) {
            int fi = tid + r * 256;
            int k = fi >> 4, c4 = (fi & 15) * 4;
            *(float4*)&Ws[k][c4] = *(const float4*)&g_Wd[(k0 + k) * 64 + c4];
        }
        __syncthreads();
        #pragma unroll
        for (int k = 0; k < 32; k++) {
            union { float4 f4; u64 d[2]; } ua0, ua1;
            ua0.f4 = *(const float4*)&As[k][ty * 8];
            ua1.f4 = *(const float4*)&As[k][ty * 8 + 4];
            u64 a0 = ua0.d[0], a1 = ua0.d[1], a2 = ua1.d[0], a3 = ua1.d[1];
            float4 b = *(const float4*)&Ws[k][tx * 4];
            u64 b0 = dup2(b.x), b1 = dup2(b.y), b2 = dup2(b.z), b3 = dup2(b.w);
            acc2[0][0] = fma2(a0, b0, acc2[0][0]); acc2[0][1] = fma2(a0, b1, acc2[0][1]);
            acc2[0][2] = fma2(a0, b2, acc2[0][2]); acc2[0][3] = fma2(a0, b3, acc2[0][3]);
            acc2[1][0] = fma2(a1, b0, acc2[1][0]); acc2[1][1] = fma2(a1, b1, acc2[1][1]);
            acc2[1][2] = fma2(a1, b2, acc2[1][2]); acc2[1][3] = fma2(a1, b3, acc2[1][3]);
            acc2[2][0] = fma2(a2, b0, acc2[2][0]); acc2[2][1] = fma2(a2, b1, acc2[2][1]);
            acc2[2][2] = fma2(a2, b2, acc2[2][2]); acc2[2][3] = fma2(a2, b3, acc2[2][3]);
            acc2[3][0] = fma2(a3, b0, acc2[3][0]); acc2[3][1] = fma2(a3, b1, acc2[3][1]);
            acc2[3][2] = fma2(a3, b2, acc2[3][2]); acc2[3][3] = fma2(a3, b3, acc2[3][3]);
        }
        __syncthreads();
    }
    if (tx * 4 < NC) {
        #pragma unroll
        for (int i = 0; i < 4; i++) {
            float2 c0 = upk2(acc2[i][0]), c1 = upk2(acc2[i][1]);
            float2 c2 = upk2(acc2[i][2]), c3 = upk2(acc2[i][3]);
            int row = row0 + ty * 8 + 2 * i;
            int c = tx * 4;
            float4 bf = *(const float4*)&g_bf[c];
            if (row < NN) {
                float4 p = *(const float4*)&g_p0[(size_t)row * NC + c];
                *(float4*)&out[(size_t)row * NC + c] =
                    make_float4(c0.x + p.x + bf.x, c1.x + p.y + bf.y,
                                c2.x + p.z + bf.z, c3.x + p.w + bf.w);
            }
            if (row + 1 < NN) {
                float4 p = *(const float4*)&g_p0[(size_t)(row + 1) * NC + c];
                *(float4*)&out[(size_t)(row + 1) * NC + c] =
                    make_float4(c0.y + p.x + bf.x, c1.y + p.y + bf.y,
                                c2.y + p.z + bf.z, c3.y + p.w + bf.w);
            }
        }
    }
}

// ---------------- launch ----------------
extern "C" void kernel_launch(void* const* d_in, const int* in_sizes, int n_in,
                              void* d_out, int out_size) {
    const float* x       = (const float*)d_in[0];
    const int*   ei32    = (const int*)d_in[1];
    const float* conv0_w = (const float*)d_in[2];
    const float* conv0_b = (const float*)d_in[3];
    const float* lin0_w  = (const float*)d_in[4];
    const float* lin0_b  = (const float*)d_in[5];
    const float* conv1_w = (const float*)d_in[6];
    const float* conv1_b = (const float*)d_in[7];
    const float* lin1_w  = (const float*)d_in[8];
    const float* lin1_b  = (const float*)d_in[9];
    const float* out_w   = (const float*)d_in[10];
    const float* out_b   = (const float*)d_in[11];
    float* out = (float*)d_out;

    k_zero<<<NB1, 256>>>(ei32);
    k_fill<<<(EE + 255) / 256, 256>>>(ei32);
    k_fusew<<<(WN + NN + 255) / 256, 256>>>(
        lin0_w, lin0_b, lin1_w, lin1_b, out_w, out_b, conv1_w);
    k_gemm0<<<(NN + 127) / 128, 256>>>(x, conv0_w);

    k_agg<<<(NN + 7) / 8, 256>>>(0, conv0_b);
    k_post0<<<(NN + 127) / 128, 256>>>();
    k_agg<<<(NN + 7) / 8, 256>>>(1, conv1_b);
    k_post1<<<(NN + 127) / 128, 256>>>(out);
}

// round 14
// speedup vs baseline: 1.0128x; 1.0128x over previous
#include <cuda_runtime.h>
#include <math.h>

#define NN   100000
#define EE   1600000
#define FIN  128
#define HID  64
#define NC   40
#define CAP  64                    // padded CSR slots per node (P[deg>64] ~ 1e-19)
#define NB1  ((NN + 255) / 256)
#define WN   (HID * 128 + HID * 64 + NC)   // 12328 weight-fold work items

typedef unsigned long long u64;

// ---------------- f32x2 packed-FMA helpers (Blackwell FFMA2) ----------------
__device__ __forceinline__ u64 dup2(float v) {
    u64 r; asm("mov.b64 %0,{%1,%1};" : "=l"(r) : "f"(v)); return r;
}
__device__ __forceinline__ u64 fma2(u64 a, u64 b, u64 c) {
    u64 d; asm("fma.rn.f32x2 %0,%1,%2,%3;" : "=l"(d) : "l"(a), "l"(b), "l"(c)); return d;
}
__device__ __forceinline__ float2 upk2(u64 v) {
    float lo, hi; asm("mov.b64 {%0,%1},%2;" : "=f"(lo), "=f"(hi) : "l"(v));
    return make_float2(lo, hi);
}

// ---------------- device scratch ----------------
__device__ int   g_is64;
__device__ int   g_cnt[NN];
__device__ int   g_esrc[(size_t)NN * CAP];       // padded CSR: src per slot
__device__ float g_dinv[NN];
__device__ __align__(16) float g_h0[NN * HID];   // x @ conv0_w ; later reused as hB
__device__ __align__(16) float g_hA[NN * HID];   // agg layer-0 output (elu'd)
__device__ __align__(16) float g_t1[NN * HID];   // hA @ conv1_w
__device__ __align__(16) float g_p0[NN * NC];    // hA @ F0
__device__ __align__(16) float g_Wc[HID * 128];  // packed [conv1_w | F0 | 0]  (64x128)
__device__ __align__(16) float g_Wd[HID * 64];   // packed [F1 | 0]            (64x64)
__device__ float g_bf[NC];

__device__ __forceinline__ float elu1(float v) { return v > 0.0f ? v : expm1f(v); }

__device__ __forceinline__ int edge_at(const int* __restrict__ ei32, long long idx) {
    return g_is64 ? ei32[idx * 2] : ei32[idx];
}

// ---------------- zero counters + dtype detect (block 0) ----------------
__global__ void k_zero(const int* __restrict__ ei32) {
    int i = blockIdx.x * blockDim.x + threadIdx.x;
    if (i < NN) g_cnt[i] = 0;
    if (blockIdx.x == 0) {
        __shared__ int nz;
        if (threadIdx.x == 0) nz = 0;
        __syncthreads();
        if (ei32[threadIdx.x * 2 + 1] != 0) atomicAdd(&nz, 1);
        __syncthreads();
        if (threadIdx.x == 0) g_is64 = (nz == 0) ? 1 : 0;
    }
}

// ---------------- single-pass fill: slot = atomic cursor on g_cnt ----------------
__global__ void k_fill(const int* __restrict__ ei32) {
    int e = blockIdx.x * blockDim.x + threadIdx.x;
    if (e < EE) {
        int s = edge_at(ei32, e);
        int d = edge_at(ei32, (long long)EE + e);
        if (s >= 0 && s < NN && d >= 0 && d < NN) {
            int c = atomicAdd(&g_cnt[d], 1);
            if (c < CAP) g_esrc[(size_t)d * CAP + c] = s;
        }
    }
}

// ---------------- fold weights (blocks covering [0,WN)) + dinv (rest) ----------------
__global__ __launch_bounds__(256) void k_fusew(
        const float* __restrict__ lin0_w, const float* __restrict__ lin0_b,
        const float* __restrict__ lin1_w, const float* __restrict__ lin1_b,
        const float* __restrict__ out_w,  const float* __restrict__ out_b,
        const float* __restrict__ conv1_w) {
    int i = blockIdx.x * blockDim.x + threadIdx.x;

    if (blockIdx.x * 256 >= WN) {        // pure-dinv block: no staging
        int node = i - WN;
        if (node < NN) g_dinv[node] = rsqrtf((float)g_cnt[node] + 1.0f);
        return;
    }

    __shared__ float ow[2 * HID * NC];   // full out_w staged (20KB)
    for (int t = threadIdx.x; t < 2 * HID * NC; t += 256) ow[t] = out_w[t];
    __syncthreads();

    if (i < HID * 128) {                         // g_Wc
        int k = i >> 7, cc = i & 127;
        float v = 0.0f;
        if (cc < 64) {
            v = conv1_w[k * HID + cc];
        } else if (cc < 104) {
            int c = cc - 64;
            float s = 0.0f;
            #pragma unroll 8
            for (int m = 0; m < HID; m++) s += __ldg(&lin0_w[k * HID + m]) * ow[m * NC + c];
            v = s;
        }
        g_Wc[i] = v;
    } else if (i < HID * 128 + HID * 64) {       // g_Wd
        int jj = i - HID * 128;
        int k = jj >> 6, cc = jj & 63;
        float v = 0.0f;
        if (cc < NC) {
            float s = 0.0f;
            #pragma unroll 8
            for (int m = 0; m < HID; m++) s += __ldg(&lin1_w[k * HID + m]) * ow[(HID + m) * NC + cc];
            v = s;
        }
        g_Wd[jj] = v;
    } else if (i < WN) {                         // g_bf
        int c = i - HID * 128 - HID * 64;
        float s = out_b[c];
        for (int m = 0; m < HID; m++)
            s += lin0_b[m] * ow[m * NC + c] + lin1_b[m] * ow[(HID + m) * NC + c];
        g_bf[c] = s;
    } else {                                     // straddle block tail: dinv
        int node = i - WN;
        if (node < NN) g_dinv[node] = rsqrtf((float)g_cnt[node] + 1.0f);
    }
}

// ---------------- GEMM0: h0 = x @ conv0_w   BM256 BN64 BK32, 8x8 micro-tile, f32x2 ----------------
__global__ __launch_bounds__(256) void k_gemm0(const float* __restrict__ x,
                                               const float* __restrict__ w) {
    __shared__ float As[32][264];   // k-major, 256 rows + pad (33.8KB)
    __shared__ float Ws[32][64];
    const int tid = threadIdx.x;
    const int row0 = blockIdx.x * 256;
    const int tx = tid & 7;         // col group: cols tx*8 .. tx*8+7
    const int ty = tid >> 3;        // row group: rows ty*8 .. ty*8+7 (4 pairs)
    const int row = row0 + tid;     // staging: one row per thread
    u64 acc2[4][8] = {};

    // prologue: prefetch tile 0 of x (32 floats = 8 float4 per thread)
    float4 pre[8];
    #pragma unroll
    for (int p = 0; p < 8; p++)
        pre[p] = (row < NN) ? *(const float4*)&x[(size_t)row * FIN + p * 4]
                            : make_float4(0, 0, 0, 0);

    #pragma unroll
    for (int t = 0; t < 4; t++) {
        const int k0 = t * 32;
        // store prefetched A tile transposed: As[k][row]
        #pragma unroll
        for (int p = 0; p < 8; p++) {
            int kk = p * 4;
            As[kk + 0][tid] = pre[p].x; As[kk + 1][tid] = pre[p].y;
            As[kk + 2][tid] = pre[p].z; As[kk + 3][tid] = pre[p].w;
        }
        // stage W tile: 32x64 = 2048 floats, 2 float4 per thread
        {
            int fi = tid;
            int k = fi >> 4, c4 = (fi & 15) * 4;
            *(float4*)&Ws[k][c4] = *(const float4*)&w[(k0 + k) * HID + c4];
            fi = tid + 256;
            k = fi >> 4; c4 = (fi & 15) * 4;
            *(float4*)&Ws[k][c4] = *(const float4*)&w[(k0 + k) * HID + c4];
        }
        __syncthreads();
        // prefetch next x tile (overlaps with FMA loop)
        if (t < 3) {
            #pragma unroll
            for (int p = 0; p < 8; p++) {
                int kk = (t + 1) * 32 + p * 4;
                pre[p] = (row < NN) ? *(const float4*)&x[(size_t)row * FIN + kk]
                                    : make_float4(0, 0, 0, 0);
            }
        }
        #pragma unroll
        for (int k = 0; k < 32; k++) {
            union { float4 f4; u64 d[2]; } ua0, ua1;
            ua0.f4 = *(const float4*)&As[k][ty * 8];
            ua1.f4 = *(const float4*)&As[k][ty * 8 + 4];
            u64 a[4] = {ua0.d[0], ua0.d[1], ua1.d[0], ua1.d[1]};
            float4 bl = *(const float4*)&Ws[k][tx * 8];
            float4 bh = *(const float4*)&Ws[k][tx * 8 + 4];
            u64 b[8] = {dup2(bl.x), dup2(bl.y), dup2(bl.z), dup2(bl.w),
                        dup2(bh.x), dup2(bh.y), dup2(bh.z), dup2(bh.w)};
            #pragma unroll
            for (int m = 0; m < 4; m++)
                #pragma unroll
                for (int n = 0; n < 8; n++)
                    acc2[m][n] = fma2(a[m], b[n], acc2[m][n]);
        }
        __syncthreads();
    }
    #pragma unroll
    for (int i = 0; i < 4; i++) {
        int orow = row0 + ty * 8 + 2 * i;
        float2 c[8];
        #pragma unroll
        for (int n = 0; n < 8; n++) c[n] = upk2(acc2[i][n]);
        if (orow < NN) {
            *(float4*)&g_h0[(size_t)orow * HID + tx * 8]     = make_float4(c[0].x, c[1].x, c[2].x, c[3].x);
            *(float4*)&g_h0[(size_t)orow * HID + tx * 8 + 4] = make_float4(c[4].x, c[5].x, c[6].x, c[7].x);
        }
        if (orow + 1 < NN) {
            *(float4*)&g_h0[(size_t)(orow + 1) * HID + tx * 8]     = make_float4(c[0].y, c[1].y, c[2].y, c[3].y);
            *(float4*)&g_h0[(size_t)(orow + 1) * HID + tx * 8 + 4] = make_float4(c[4].y, c[5].y, c[6].y, c[7].y);
        }
    }
}

// ---------------- gather-aggregate: one warp per node, serial walk (R12 form) ----------------
__global__ __launch_bounds__(256) void k_agg(int layer, const float* __restrict__ bias) {
    const float2* feat = (layer == 0) ? (const float2*)g_h0 : (const float2*)g_t1;
    float2*       outh = (layer == 0) ? (float2*)g_hA      : (float2*)g_h0;
    int warp = threadIdx.x >> 5;
    int lane = threadIdx.x & 31;
    int node = blockIdx.x * 8 + warp;
    if (node >= NN) return;

    const int* el = &g_esrc[(size_t)node * CAP];
    int cnt  = g_cnt[node];
    if (cnt > CAP) cnt = CAP;
    float dd = g_dinv[node];
    float2 acc = make_float2(0.0f, 0.0f);

    #pragma unroll 4
    for (int j = 0; j < cnt; j++) {
        int s = __ldg(&el[j]);
        float c = dd * __ldg(&g_dinv[s]);
        float2 v = __ldg(&feat[(size_t)s * 32 + lane]);
        acc.x = fmaf(c, v.x, acc.x);
        acc.y = fmaf(c, v.y, acc.y);
    }
    {   // self-loop
        float2 v = __ldg(&feat[(size_t)node * 32 + lane]);
        float c = dd * dd;
        acc.x = fmaf(c, v.x, acc.x);
        acc.y = fmaf(c, v.y, acc.y);
    }
    float2 bb = __ldg(&((const float2*)bias)[lane]);
    outh[(size_t)node * 32 + lane] = make_float2(elu1(acc.x + bb.x), elu1(acc.y + bb.y));
}

// ---------------- post0: [t1|p0] = hA @ g_Wc   BM128 BN128 BK32, f32x2 ----------------
__global__ __launch_bounds__(256) void k_post0() {
    __shared__ float As[32][132];
    __shared__ float Ws[32][128];
    const int tid = threadIdx.x;
    const int row0 = blockIdx.x * 128;
    const int tx = tid & 15, ty = tid >> 4;
    const int lrow = tid & 127, lkc = tid >> 7;
    u64 accL[4][4] = {}, accR[4][4] = {};

    for (int k0 = 0; k0 < HID; k0 += 32) {
        #pragma unroll
        for (int p = 0; p < 4; p++) {
            int kk = lkc * 16 + p * 4;
            int row = row0 + lrow;
            float4 v = (row < NN) ? *(const float4*)&g_hA[(size_t)row * HID + k0 + kk]
                                  : make_float4(0, 0, 0, 0);
            As[kk + 0][lrow] = v.x; As[kk + 1][lrow] = v.y;
            As[kk + 2][lrow] = v.z; As[kk + 3][lrow] = v.w;
        }
        #pragma unroll
        for (int r = 0; r < 4; r++) {
            int fi = tid + r * 256;
            int k = fi >> 5, c4 = (fi & 31) * 4;
            *(float4*)&Ws[k][c4] = *(const float4*)&g_Wc[(k0 + k) * 128 + c4];
        }
        __syncthreads();
        #pragma unroll
        for (int k = 0; k < 32; k++) {
            union { float4 f4; u64 d[2]; } ua0, ua1;
            ua0.f4 = *(const float4*)&As[k][ty * 8];
            ua1.f4 = *(const float4*)&As[k][ty * 8 + 4];
            u64 a0 = ua0.d[0], a1 = ua0.d[1], a2 = ua1.d[0], a3 = ua1.d[1];
            float4 bl = *(const float4*)&Ws[k][tx * 4];
            float4 br = *(const float4*)&Ws[k][64 + tx * 4];
            u64 l0 = dup2(bl.x), l1 = dup2(bl.y), l2 = dup2(bl.z), l3 = dup2(bl.w);
            u64 r0 = dup2(br.x), r1 = dup2(br.y), r2 = dup2(br.z), r3 = dup2(br.w);
            accL[0][0] = fma2(a0, l0, accL[0][0]); accL[0][1] = fma2(a0, l1, accL[0][1]);
            accL[0][2] = fma2(a0, l2, accL[0][2]); accL[0][3] = fma2(a0, l3, accL[0][3]);
            accL[1][0] = fma2(a1, l0, accL[1][0]); accL[1][1] = fma2(a1, l1, accL[1][1]);
            accL[1][2] = fma2(a1, l2, accL[1][2]); accL[1][3] = fma2(a1, l3, accL[1][3]);
            accL[2][0] = fma2(a2, l0, accL[2][0]); accL[2][1] = fma2(a2, l1, accL[2][1]);
            accL[2][2] = fma2(a2, l2, accL[2][2]); accL[2][3] = fma2(a2, l3, accL[2][3]);
            accL[3][0] = fma2(a3, l0, accL[3][0]); accL[3][1] = fma2(a3, l1, accL[3][1]);
            accL[3][2] = fma2(a3, l2, accL[3][2]); accL[3][3] = fma2(a3, l3, accL[3][3]);
            accR[0][0] = fma2(a0, r0, accR[0][0]); accR[0][1] = fma2(a0, r1, accR[0][1]);
            accR[0][2] = fma2(a0, r2, accR[0][2]); accR[0][3] = fma2(a0, r3, accR[0][3]);
            accR[1][0] = fma2(a1, r0, accR[1][0]); accR[1][1] = fma2(a1, r1, accR[1][1]);
            accR[1][2] = fma2(a1, r2, accR[1][2]); accR[1][3] = fma2(a1, r3, accR[1][3]);
            accR[2][0] = fma2(a2, r0, accR[2][0]); accR[2][1] = fma2(a2, r1, accR[2][1]);
            accR[2][2] = fma2(a2, r2, accR[2][2]); accR[2][3] = fma2(a2, r3, accR[2][3]);
            accR[3][0] = fma2(a3, r0, accR[3][0]); accR[3][1] = fma2(a3, r1, accR[3][1]);
            accR[3][2] = fma2(a3, r2, accR[3][2]); accR[3][3] = fma2(a3, r3, accR[3][3]);
        }
        __syncthreads();
    }
    #pragma unroll
    for (int i = 0; i < 4; i++) {
        float2 l0 = upk2(accL[i][0]), l1 = upk2(accL[i][1]);
        float2 l2 = upk2(accL[i][2]), l3 = upk2(accL[i][3]);
        float2 r0 = upk2(accR[i][0]), r1 = upk2(accR[i][1]);
        float2 r2 = upk2(accR[i][2]), r3 = upk2(accR[i][3]);
        int row = row0 + ty * 8 + 2 * i;
        if (row < NN) {
            *(float4*)&g_t1[(size_t)row * HID + tx * 4] = make_float4(l0.x, l1.x, l2.x, l3.x);
            if (tx < 10)
                *(float4*)&g_p0[(size_t)row * NC + tx * 4] = make_float4(r0.x, r1.x, r2.x, r3.x);
        }
        if (row + 1 < NN) {
            *(float4*)&g_t1[(size_t)(row + 1) * HID + tx * 4] = make_float4(l0.y, l1.y, l2.y, l3.y);
            if (tx < 10)
                *(float4*)&g_p0[(size_t)(row + 1) * NC + tx * 4] = make_float4(r0.y, r1.y, r2.y, r3.y);
        }
    }
}

// ---------------- post1: out = p0 + hB @ g_Wd + bf   BM128 BN64 BK32, f32x2 ----------------
__global__ __launch_bounds__(256) void k_post1(float* __restrict__ out) {
    __shared__ float As[32][132];
    __shared__ float Ws[32][64];
    const int tid = threadIdx.x;
    const int row0 = blockIdx.x * 128;
    const int tx = tid & 15, ty = tid >> 4;
    const int lrow = tid & 127, lkc = tid >> 7;
    u64 acc2[4][4] = {};

    for (int k0 = 0; k0 < HID; k0 += 32) {
        #pragma unroll
        for (int p = 0; p < 4; p++) {
            int kk = lkc * 16 + p * 4;
            int row = row0 + lrow;
            float4 v = (row < NN) ? *(const float4*)&g_h0[(size_t)row * HID + k0 + kk]
                                  : make_float4(0, 0, 0, 0);
            As[kk + 0][lrow] = v.x; As[kk + 1][lrow] = v.y;
            As[kk + 2][lrow] = v.z; As[kk + 3][lrow] = v.w;
        }
        #pragma unroll
        for (int r = 0; r < 2; r++) {
            int fi = tid + r * 256;
            int k = fi >> 4, c4 = (fi & 15) * 4;
            *(float4*)&Ws[k][c4] = *(const float4*)&g_Wd[(k0 + k) * 64 + c4];
        }
        __syncthreads();
        #pragma unroll
        for (int k = 0; k < 32; k++) {
            union { float4 f4; u64 d[2]; } ua0, ua1;
            ua0.f4 = *(const float4*)&As[k][ty * 8];
            ua1.f4 = *(const float4*)&As[k][ty * 8 + 4];
            u64 a0 = ua0.d[0], a1 = ua0.d[1], a2 = ua1.d[0], a3 = ua1.d[1];
            float4 b = *(const float4*)&Ws[k][tx * 4];
            u64 b0 = dup2(b.x), b1 = dup2(b.y), b2 = dup2(b.z), b3 = dup2(b.w);
            acc2[0][0] = fma2(a0, b0, acc2[0][0]); acc2[0][1] = fma2(a0, b1, acc2[0][1]);
            acc2[0][2] = fma2(a0, b2, acc2[0][2]); acc2[0][3] = fma2(a0, b3, acc2[0][3]);
            acc2[1][0] = fma2(a1, b0, acc2[1][0]); acc2[1][1] = fma2(a1, b1, acc2[1][1]);
            acc2[1][2] = fma2(a1, b2, acc2[1][2]); acc2[1][3] = fma2(a1, b3, acc2[1][3]);
            acc2[2][0] = fma2(a2, b0, acc2[2][0]); acc2[2][1] = fma2(a2, b1, acc2[2][1]);
            acc2[2][2] = fma2(a2, b2, acc2[2][2]); acc2[2][3] = fma2(a2, b3, acc2[2][3]);
            acc2[3][0] = fma2(a3, b0, acc2[3][0]); acc2[3][1] = fma2(a3, b1, acc2[3][1]);
            acc2[3][2] = fma2(a3, b2, acc2[3][2]); acc2[3][3] = fma2(a3, b3, acc2[3][3]);
        }
        __syncthreads();
    }
    if (tx * 4 < NC) {
        #pragma unroll
        for (int i = 0; i < 4; i++) {
            float2 c0 = upk2(acc2[i][0]), c1 = upk2(acc2[i][1]);
            float2 c2 = upk2(acc2[i][2]), c3 = upk2(acc2[i][3]);
            int row = row0 + ty * 8 + 2 * i;
            int c = tx * 4;
            float4 bf = *(const float4*)&g_bf[c];
            if (row < NN) {
                float4 p = *(const float4*)&g_p0[(size_t)row * NC + c];
                *(float4*)&out[(size_t)row * NC + c] =
                    make_float4(c0.x + p.x + bf.x, c1.x + p.y + bf.y,
                                c2.x + p.z + bf.z, c3.x + p.w + bf.w);
            }
            if (row + 1 < NN) {
                float4 p = *(const float4*)&g_p0[(size_t)(row + 1) * NC + c];
                *(float4*)&out[(size_t)(row + 1) * NC + c] =
                    make_float4(c0.y + p.x + bf.x, c1.y + p.y + bf.y,
                                c2.y + p.z + bf.z, c3.y + p.w + bf.w);
            }
        }
    }
}

// ---------------- launch ----------------
extern "C" void kernel_launch(void* const* d_in, const int* in_sizes, int n_in,
                              void* d_out, int out_size) {
    const float* x       = (const float*)d_in[0];
    const int*   ei32    = (const int*)d_in[1];
    const float* conv0_w = (const float*)d_in[2];
    const float* conv0_b = (const float*)d_in[3];
    const float* lin0_w  = (const float*)d_in[4];
    const float* lin0_b  = (const float*)d_in[5];
    const float* conv1_w = (const float*)d_in[6];
    const float* conv1_b = (const float*)d_in[7];
    const float* lin1_w  = (const float*)d_in[8];
    const float* lin1_b  = (const float*)d_in[9];
    const float* out_w   = (const float*)d_in[10];
    const float* out_b   = (const float*)d_in[11];
    float* out = (float*)d_out;

    k_zero<<<NB1, 256>>>(ei32);
    k_fill<<<(EE + 255) / 256, 256>>>(ei32);
    k_fusew<<<(WN + NN + 255) / 256, 256>>>(
        lin0_w, lin0_b, lin1_w, lin1_b, out_w, out_b, conv1_w);
    k_gemm0<<<(NN + 255) / 256, 256>>>(x, conv0_w);

    k_agg<<<(NN + 7) / 8, 256>>>(0, conv0_b);
    k_post0<<<(NN + 127) / 128, 256>>>();
    k_agg<<<(NN + 7) / 8, 256>>>(1, conv1_b);
    k_post1<<<(NN + 127) / 128, 256>>>(out);
}

// round 15
// speedup vs baseline: 1.0553x; 1.0420x over previous
#include <cuda_runtime.h>
#include <math.h>

#define NN   100000
#define EE   1600000
#define FIN  128
#define HID  64
#define NC   40
#define CAP  64                    // padded CSR slots per node (P[deg>64] ~ 1e-19)
#define NB1  ((NN + 255) / 256)
#define WN   (HID * 128 + HID * 64 + NC)   // 12328 weight-fold work items

typedef unsigned long long u64;

// ---------------- f32x2 packed-FMA helpers (Blackwell FFMA2) ----------------
__device__ __forceinline__ u64 dup2(float v) {
    u64 r; asm("mov.b64 %0,{%1,%1};" : "=l"(r) : "f"(v)); return r;
}
__device__ __forceinline__ u64 fma2(u64 a, u64 b, u64 c) {
    u64 d; asm("fma.rn.f32x2 %0,%1,%2,%3;" : "=l"(d) : "l"(a), "l"(b), "l"(c)); return d;
}
__device__ __forceinline__ float2 upk2(u64 v) {
    float lo, hi; asm("mov.b64 {%0,%1},%2;" : "=f"(lo), "=f"(hi) : "l"(v));
    return make_float2(lo, hi);
}

// ---------------- device scratch ----------------
__device__ int   g_is64;
__device__ int   g_cnt[NN];
__device__ int   g_esrc[(size_t)NN * CAP];       // padded CSR: src per slot
__device__ float g_dinv[NN];
__device__ __align__(16) float g_h0[NN * HID];   // x @ conv0_w ; later reused as hB
__device__ __align__(16) float g_hA[NN * HID];   // agg layer-0 output (elu'd)
__device__ __align__(16) float g_t1[NN * HID];   // hA @ conv1_w
__device__ __align__(16) float g_p0[NN * NC];    // hA @ F0
__device__ __align__(16) float g_Wc[HID * 128];  // packed [conv1_w | F0 | 0]  (64x128)
__device__ __align__(16) float g_Wd[HID * 64];   // packed [F1 | 0]            (64x64)
__device__ float g_bf[NC];

__device__ __forceinline__ float elu1(float v) { return v > 0.0f ? v : expm1f(v); }

__device__ __forceinline__ int edge_at(const int* __restrict__ ei32, long long idx) {
    return g_is64 ? ei32[idx * 2] : ei32[idx];
}

// ---------------- zero counters + dtype detect (block 0) ----------------
__global__ void k_zero(const int* __restrict__ ei32) {
    int i = blockIdx.x * blockDim.x + threadIdx.x;
    if (i < NN) g_cnt[i] = 0;
    if (blockIdx.x == 0) {
        __shared__ int nz;
        if (threadIdx.x == 0) nz = 0;
        __syncthreads();
        if (ei32[threadIdx.x * 2 + 1] != 0) atomicAdd(&nz, 1);
        __syncthreads();
        if (threadIdx.x == 0) g_is64 = (nz == 0) ? 1 : 0;
    }
}

// ---------------- single-pass fill: slot = atomic cursor on g_cnt ----------------
__global__ void k_fill(const int* __restrict__ ei32) {
    int e = blockIdx.x * blockDim.x + threadIdx.x;
    if (e < EE) {
        int s = edge_at(ei32, e);
        int d = edge_at(ei32, (long long)EE + e);
        if (s >= 0 && s < NN && d >= 0 && d < NN) {
            int c = atomicAdd(&g_cnt[d], 1);
            if (c < CAP) g_esrc[(size_t)d * CAP + c] = s;
        }
    }
}

// dinv from counts (runs on CSR stream after fill)
__global__ void k_dinv() {
    int i = blockIdx.x * blockDim.x + threadIdx.x;
    if (i < NN) g_dinv[i] = rsqrtf((float)g_cnt[i] + 1.0f);
}

// ---------------- fold + pack weights (49 blocks only) ----------------
__global__ __launch_bounds__(256) void k_fusew(
        const float* __restrict__ lin0_w, const float* __restrict__ lin0_b,
        const float* __restrict__ lin1_w, const float* __restrict__ lin1_b,
        const float* __restrict__ out_w,  const float* __restrict__ out_b,
        const float* __restrict__ conv1_w) {
    __shared__ float ow[2 * HID * NC];   // full out_w staged (20KB)
    for (int t = threadIdx.x; t < 2 * HID * NC; t += 256) ow[t] = out_w[t];
    __syncthreads();

    int i = blockIdx.x * blockDim.x + threadIdx.x;
    if (i < HID * 128) {                         // g_Wc
        int k = i >> 7, cc = i & 127;
        float v = 0.0f;
        if (cc < 64) {
            v = conv1_w[k * HID + cc];
        } else if (cc < 104) {
            int c = cc - 64;
            float s = 0.0f;
            #pragma unroll 8
            for (int m = 0; m < HID; m++) s += __ldg(&lin0_w[k * HID + m]) * ow[m * NC + c];
            v = s;
        }
        g_Wc[i] = v;
    } else if (i < HID * 128 + HID * 64) {       // g_Wd
        int jj = i - HID * 128;
        int k = jj >> 6, cc = jj & 63;
        float v = 0.0f;
        if (cc < NC) {
            float s = 0.0f;
            #pragma unroll 8
            for (int m = 0; m < HID; m++) s += __ldg(&lin1_w[k * HID + m]) * ow[(HID + m) * NC + cc];
            v = s;
        }
        g_Wd[jj] = v;
    } else if (i < WN) {                         // g_bf
        int c = i - HID * 128 - HID * 64;
        float s = out_b[c];
        for (int m = 0; m < HID; m++)
            s += lin0_b[m] * ow[m * NC + c] + lin1_b[m] * ow[(HID + m) * NC + c];
        g_bf[c] = s;
    }
}

// ---------------- GEMM0 (R12 form): h0 = x @ conv0_w   BM128 BN64 BK32, f32x2, x-prefetch ----------------
__global__ __launch_bounds__(256) void k_gemm0(const float* __restrict__ x,
                                               const float* __restrict__ w) {
    __shared__ float As[32][132];   // k-major
    __shared__ float Ws[32][64];
    const int tid = threadIdx.x;
    const int row0 = blockIdx.x * 128;
    const int tx = tid & 15, ty = tid >> 4;
    const int lrow = tid & 127, lkc = tid >> 7;
    const int row = row0 + lrow;
    u64 acc2[4][4] = {};

    float4 pre[4];
    #pragma unroll
    for (int p = 0; p < 4; p++) {
        int kk = lkc * 16 + p * 4;
        pre[p] = (row < NN) ? *(const float4*)&x[(size_t)row * FIN + kk]
                            : make_float4(0, 0, 0, 0);
    }

    #pragma unroll
    for (int t = 0; t < 4; t++) {
        const int k0 = t * 32;
        #pragma unroll
        for (int p = 0; p < 4; p++) {
            int kk = lkc * 16 + p * 4;
            As[kk + 0][lrow] = pre[p].x; As[kk + 1][lrow] = pre[p].y;
            As[kk + 2][lrow] = pre[p].z; As[kk + 3][lrow] = pre[p].w;
        }
        #pragma unroll
        for (int r = 0; r < 2; r++) {
            int fi = tid + r * 256;
            int k = fi >> 4, c4 = (fi & 15) * 4;
            *(float4*)&Ws[k][c4] = *(const float4*)&w[(k0 + k) * HID + c4];
        }
        __syncthreads();
        if (t < 3) {
            #pragma unroll
            for (int p = 0; p < 4; p++) {
                int kk = (t + 1) * 32 + lkc * 16 + p * 4;
                pre[p] = (row < NN) ? *(const float4*)&x[(size_t)row * FIN + kk]
                                    : make_float4(0, 0, 0, 0);
            }
        }
        #pragma unroll
        for (int k = 0; k < 32; k++) {
            union { float4 f4; u64 d[2]; } ua0, ua1;
            ua0.f4 = *(const float4*)&As[k][ty * 8];
            ua1.f4 = *(const float4*)&As[k][ty * 8 + 4];
            u64 a0 = ua0.d[0], a1 = ua0.d[1], a2 = ua1.d[0], a3 = ua1.d[1];
            float4 b = *(const float4*)&Ws[k][tx * 4];
            u64 b0 = dup2(b.x), b1 = dup2(b.y), b2 = dup2(b.z), b3 = dup2(b.w);
            acc2[0][0] = fma2(a0, b0, acc2[0][0]); acc2[0][1] = fma2(a0, b1, acc2[0][1]);
            acc2[0][2] = fma2(a0, b2, acc2[0][2]); acc2[0][3] = fma2(a0, b3, acc2[0][3]);
            acc2[1][0] = fma2(a1, b0, acc2[1][0]); acc2[1][1] = fma2(a1, b1, acc2[1][1]);
            acc2[1][2] = fma2(a1, b2, acc2[1][2]); acc2[1][3] = fma2(a1, b3, acc2[1][3]);
            acc2[2][0] = fma2(a2, b0, acc2[2][0]); acc2[2][1] = fma2(a2, b1, acc2[2][1]);
            acc2[2][2] = fma2(a2, b2, acc2[2][2]); acc2[2][3] = fma2(a2, b3, acc2[2][3]);
            acc2[3][0] = fma2(a3, b0, acc2[3][0]); acc2[3][1] = fma2(a3, b1, acc2[3][1]);
            acc2[3][2] = fma2(a3, b2, acc2[3][2]); acc2[3][3] = fma2(a3, b3, acc2[3][3]);
        }
        __syncthreads();
    }
    #pragma unroll
    for (int i = 0; i < 4; i++) {
        float2 c0 = upk2(acc2[i][0]), c1 = upk2(acc2[i][1]);
        float2 c2 = upk2(acc2[i][2]), c3 = upk2(acc2[i][3]);
        int orow = row0 + ty * 8 + 2 * i;
        if (orow < NN)
            *(float4*)&g_h0[(size_t)orow * HID + tx * 4] = make_float4(c0.x, c1.x, c2.x, c3.x);
        if (orow + 1 < NN)
            *(float4*)&g_h0[(size_t)(orow + 1) * HID + tx * 4] = make_float4(c0.y, c1.y, c2.y, c3.y);
    }
}

// ---------------- gather-aggregate (R12 form): one warp per node, serial walk ----------------
__global__ __launch_bounds__(256) void k_agg(int layer, const float* __restrict__ bias) {
    const float2* feat = (layer == 0) ? (const float2*)g_h0 : (const float2*)g_t1;
    float2*       outh = (layer == 0) ? (float2*)g_hA      : (float2*)g_h0;
    int warp = threadIdx.x >> 5;
    int lane = threadIdx.x & 31;
    int node = blockIdx.x * 8 + warp;
    if (node >= NN) return;

    const int* el = &g_esrc[(size_t)node * CAP];
    int cnt  = g_cnt[node];
    if (cnt > CAP) cnt = CAP;
    float dd = g_dinv[node];
    float2 acc = make_float2(0.0f, 0.0f);

    #pragma unroll 4
    for (int j = 0; j < cnt; j++) {
        int s = __ldg(&el[j]);
        float c = dd * __ldg(&g_dinv[s]);
        float2 v = __ldg(&feat[(size_t)s * 32 + lane]);
        acc.x = fmaf(c, v.x, acc.x);
        acc.y = fmaf(c, v.y, acc.y);
    }
    {   // self-loop
        float2 v = __ldg(&feat[(size_t)node * 32 + lane]);
        float c = dd * dd;
        acc.x = fmaf(c, v.x, acc.x);
        acc.y = fmaf(c, v.y, acc.y);
    }
    float2 bb = __ldg(&((const float2*)bias)[lane]);
    outh[(size_t)node * 32 + lane] = make_float2(elu1(acc.x + bb.x), elu1(acc.y + bb.y));
}

// ---------------- post0 (R12 form): [t1|p0] = hA @ g_Wc   BM128 BN128 BK32, f32x2 ----------------
__global__ __launch_bounds__(256) void k_post0() {
    __shared__ float As[32][132];
    __shared__ float Ws[32][128];
    const int tid = threadIdx.x;
    const int row0 = blockIdx.x * 128;
    const int tx = tid & 15, ty = tid >> 4;
    const int lrow = tid & 127, lkc = tid >> 7;
    u64 accL[4][4] = {}, accR[4][4] = {};

    for (int k0 = 0; k0 < HID; k0 += 32) {
        #pragma unroll
        for (int p = 0; p < 4; p++) {
            int kk = lkc * 16 + p * 4;
            int row = row0 + lrow;
            float4 v = (row < NN) ? *(const float4*)&g_hA[(size_t)row * HID + k0 + kk]
                                  : make_float4(0, 0, 0, 0);
            As[kk + 0][lrow] = v.x; As[kk + 1][lrow] = v.y;
            As[kk + 2][lrow] = v.z; As[kk + 3][lrow] = v.w;
        }
        #pragma unroll
        for (int r = 0; r < 4; r++) {
            int fi = tid + r * 256;
            int k = fi >> 5, c4 = (fi & 31) * 4;
            *(float4*)&Ws[k][c4] = *(const float4*)&g_Wc[(k0 + k) * 128 + c4];
        }
        __syncthreads();
        #pragma unroll
        for (int k = 0; k < 32; k++) {
            union { float4 f4; u64 d[2]; } ua0, ua1;
            ua0.f4 = *(const float4*)&As[k][ty * 8];
            ua1.f4 = *(const float4*)&As[k][ty * 8 + 4];
            u64 a0 = ua0.d[0], a1 = ua0.d[1], a2 = ua1.d[0], a3 = ua1.d[1];
            float4 bl = *(const float4*)&Ws[k][tx * 4];
            float4 br = *(const float4*)&Ws[k][64 + tx * 4];
            u64 l0 = dup2(bl.x), l1 = dup2(bl.y), l2 = dup2(bl.z), l3 = dup2(bl.w);
            u64 r0 = dup2(br.x), r1 = dup2(br.y), r2 = dup2(br.z), r3 = dup2(br.w);
            accL[0][0] = fma2(a0, l0, accL[0][0]); accL[0][1] = fma2(a0, l1, accL[0][1]);
            accL[0][2] = fma2(a0, l2, accL[0][2]); accL[0][3] = fma2(a0, l3, accL[0][3]);
            accL[1][0] = fma2(a1, l0, accL[1][0]); accL[1][1] = fma2(a1, l1, accL[1][1]);
            accL[1][2] = fma2(a1, l2, accL[1][2]); accL[1][3] = fma2(a1, l3, accL[1][3]);
            accL[2][0] = fma2(a2, l0, accL[2][0]); accL[2][1] = fma2(a2, l1, accL[2][1]);
            accL[2][2] = fma2(a2, l2, accL[2][2]); accL[2][3] = fma2(a2, l3, accL[2][3]);
            accL[3][0] = fma2(a3, l0, accL[3][0]); accL[3][1] = fma2(a3, l1, accL[3][1]);
            accL[3][2] = fma2(a3, l2, accL[3][2]); accL[3][3] = fma2(a3, l3, accL[3][3]);
            accR[0][0] = fma2(a0, r0, accR[0][0]); accR[0][1] = fma2(a0, r1, accR[0][1]);
            accR[0][2] = fma2(a0, r2, accR[0][2]); accR[0][3] = fma2(a0, r3, accR[0][3]);
            accR[1][0] = fma2(a1, r0, accR[1][0]); accR[1][1] = fma2(a1, r1, accR[1][1]);
            accR[1][2] = fma2(a1, r2, accR[1][2]); accR[1][3] = fma2(a1, r3, accR[1][3]);
            accR[2][0] = fma2(a2, r0, accR[2][0]); accR[2][1] = fma2(a2, r1, accR[2][1]);
            accR[2][2] = fma2(a2, r2, accR[2][2]); accR[2][3] = fma2(a2, r3, accR[2][3]);
            accR[3][0] = fma2(a3, r0, accR[3][0]); accR[3][1] = fma2(a3, r1, accR[3][1]);
            accR[3][2] = fma2(a3, r2, accR[3][2]); accR[3][3] = fma2(a3, r3, accR[3][3]);
        }
        __syncthreads();
    }
    #pragma unroll
    for (int i = 0; i < 4; i++) {
        float2 l0 = upk2(accL[i][0]), l1 = upk2(accL[i][1]);
        float2 l2 = upk2(accL[i][2]), l3 = upk2(accL[i][3]);
        float2 r0 = upk2(accR[i][0]), r1 = upk2(accR[i][1]);
        float2 r2 = upk2(accR[i][2]), r3 = upk2(accR[i][3]);
        int row = row0 + ty * 8 + 2 * i;
        if (row < NN) {
            *(float4*)&g_t1[(size_t)row * HID + tx * 4] = make_float4(l0.x, l1.x, l2.x, l3.x);
            if (tx < 10)
                *(float4*)&g_p0[(size_t)row * NC + tx * 4] = make_float4(r0.x, r1.x, r2.x, r3.x);
        }
        if (row + 1 < NN) {
            *(float4*)&g_t1[(size_t)(row + 1) * HID + tx * 4] = make_float4(l0.y, l1.y, l2.y, l3.y);
            if (tx < 10)
                *(float4*)&g_p0[(size_t)(row + 1) * NC + tx * 4] = make_float4(r0.y, r1.y, r2.y, r3.y);
        }
    }
}

// ---------------- post1 (R12 form): out = p0 + hB @ g_Wd + bf   BM128 BN64 BK32, f32x2 ----------------
__global__ __launch_bounds__(256) void k_post1(float* __restrict__ out) {
    __shared__ float As[32][132];
    __shared__ float Ws[32][64];
    const int tid = threadIdx.x;
    const int row0 = blockIdx.x * 128;
    const int tx = tid & 15, ty = tid >> 4;
    const int lrow = tid & 127, lkc = tid >> 7;
    u64 acc2[4][4] = {};

    for (int k0 = 0; k0 < HID; k0 += 32) {
        #pragma unroll
        for (int p = 0; p < 4; p++) {
            int kk = lkc * 16 + p * 4;
            int row = row0 + lrow;
            float4 v = (row < NN) ? *(const float4*)&g_h0[(size_t)row * HID + k0 + kk]
                                  : make_float4(0, 0, 0, 0);
            As[kk + 0][lrow] = v.x; As[kk + 1][lrow] = v.y;
            As[kk + 2][lrow] = v.z; As[kk + 3][lrow] = v.w;
        }
        #pragma unroll
        for (int r = 0; r < 2; r++) {
            int fi = tid + r * 256;
            int k = fi >> 4, c4 = (fi & 15) * 4;
            *(float4*)&Ws[k][c4] = *(const float4*)&g_Wd[(k0 + k) * 64 + c4];
        }
        __syncthreads();
        #pragma unroll
        for (int k = 0; k < 32; k++) {
            union { float4 f4; u64 d[2]; } ua0, ua1;
            ua0.f4 = *(const float4*)&As[k][ty * 8];
            ua1.f4 = *(const float4*)&As[k][ty * 8 + 4];
            u64 a0 = ua0.d[0], a1 = ua0.d[1], a2 = ua1.d[0], a3 = ua1.d[1];
            float4 b = *(const float4*)&Ws[k][tx * 4];
            u64 b0 = dup2(b.x), b1 = dup2(b.y), b2 = dup2(b.z), b3 = dup2(b.w);
            acc2[0][0] = fma2(a0, b0, acc2[0][0]); acc2[0][1] = fma2(a0, b1, acc2[0][1]);
            acc2[0][2] = fma2(a0, b2, acc2[0][2]); acc2[0][3] = fma2(a0, b3, acc2[0][3]);
            acc2[1][0] = fma2(a1, b0, acc2[1][0]); acc2[1][1] = fma2(a1, b1, acc2[1][1]);
            acc2[1][2] = fma2(a1, b2, acc2[1][2]); acc2[1][3] = fma2(a1, b3, acc2[1][3]);
            acc2[2][0] = fma2(a2, b0, acc2[2][0]); acc2[2][1] = fma2(a2, b1, acc2[2][1]);
            acc2[2][2] = fma2(a2, b2, acc2[2][2]); acc2[2][3] = fma2(a2, b3, acc2[2][3]);
            acc2[3][0] = fma2(a3, b0, acc2[3][0]); acc2[3][1] = fma2(a3, b1, acc2[3][1]);
            acc2[3][2] = fma2(a3, b2, acc2[3][2]); acc2[3][3] = fma2(a3, b3, acc2[3][3]);
        }
        __syncthreads();
    }
    if (tx * 4 < NC) {
        #pragma unroll
        for (int i = 0; i < 4; i++) {
            float2 c0 = upk2(acc2[i][0]), c1 = upk2(acc2[i][1]);
            float2 c2 = upk2(acc2[i][2]), c3 = upk2(acc2[i][3]);
            int row = row0 + ty * 8 + 2 * i;
            int c = tx * 4;
            float4 bf = *(const float4*)&g_bf[c];
            if (row < NN) {
                float4 p = *(const float4*)&g_p0[(size_t)row * NC + c];
                *(float4*)&out[(size_t)row * NC + c] =
                    make_float4(c0.x + p.x + bf.x, c1.x + p.y + bf.y,
                                c2.x + p.z + bf.z, c3.x + p.w + bf.w);
            }
            if (row + 1 < NN) {
                float4 p = *(const float4*)&g_p0[(size_t)(row + 1) * NC + c];
                *(float4*)&out[(size_t)(row + 1) * NC + c] =
                    make_float4(c0.y + p.x + bf.x, c1.y + p.y + bf.y,
                                c2.y + p.z + bf.z, c3.y + p.w + bf.w);
            }
        }
    }
}

// ---------------- launch: CSR build forked onto a second stream ----------------
extern "C" void kernel_launch(void* const* d_in, const int* in_sizes, int n_in,
                              void* d_out, int out_size) {
    const float* x       = (const float*)d_in[0];
    const int*   ei32    = (const int*)d_in[1];
    const float* conv0_w = (const float*)d_in[2];
    const float* conv0_b = (const float*)d_in[3];
    const float* lin0_w  = (const float*)d_in[4];
    const float* lin0_b  = (const float*)d_in[5];
    const float* conv1_w = (const float*)d_in[6];
    const float* conv1_b = (const float*)d_in[7];
    const float* lin1_w  = (const float*)d_in[8];
    const float* lin1_b  = (const float*)d_in[9];
    const float* out_w   = (const float*)d_in[10];
    const float* out_b   = (const float*)d_in[11];
    float* out = (float*)d_out;

    static cudaStream_t s2 = nullptr;
    static cudaEvent_t evFork = nullptr, evJoin = nullptr;
    if (s2 == nullptr) {
        cudaStreamCreateWithFlags(&s2, cudaStreamNonBlocking);
        cudaEventCreateWithFlags(&evFork, cudaEventDisableTiming);
        cudaEventCreateWithFlags(&evJoin, cudaEventDisableTiming);
    }

    // fork: CSR build on s2, dense front on main stream
    cudaEventRecord(evFork, 0);
    cudaStreamWaitEvent(s2, evFork, 0);

    k_zero<<<NB1, 256, 0, s2>>>(ei32);
    k_fill<<<(EE + 255) / 256, 256, 0, s2>>>(ei32);
    k_dinv<<<NB1, 256, 0, s2>>>();
    cudaEventRecord(evJoin, s2);

    k_fusew<<<(WN + 255) / 256, 256>>>(
        lin0_w, lin0_b, lin1_w, lin1_b, out_w, out_b, conv1_w);
    k_gemm0<<<(NN + 127) / 128, 256>>>(x, conv0_w);

    // join: agg needs both CSR and h0
    cudaStreamWaitEvent(0, evJoin, 0);

    k_agg<<<(NN + 7) / 8, 256>>>(0, conv0_b);
    k_post0<<<(NN + 127) / 128, 256>>>();
    k_agg<<<(NN + 7) / 8, 256>>>(1, conv1_b);
    k_post1<<<(NN + 127) / 128, 256>>>(out);
}

// round 16
// speedup vs baseline: 1.1664x; 1.1053x over previous
#include <cuda_runtime.h>
#include <math.h>

#define NN   100000
#define EE   1600000
#define FIN  128
#define HID  64
#define NC   40
#define CAP  64                    // padded CSR slots per node (P[deg>64] ~ 1e-19)
#define NB1  ((NN + 255) / 256)
#define WN   (HID * 128 + HID * 64 + NC)   // 12328 weight-fold work items

typedef unsigned long long u64;

// ---------------- f32x2 packed-FMA helpers (Blackwell FFMA2) ----------------
__device__ __forceinline__ u64 dup2(float v) {
    u64 r; asm("mov.b64 %0,{%1,%1};" : "=l"(r) : "f"(v)); return r;
}
__device__ __forceinline__ u64 fma2(u64 a, u64 b, u64 c) {
    u64 d; asm("fma.rn.f32x2 %0,%1,%2,%3;" : "=l"(d) : "l"(a), "l"(b), "l"(c)); return d;
}
__device__ __forceinline__ float2 upk2(u64 v) {
    float lo, hi; asm("mov.b64 {%0,%1},%2;" : "=f"(lo), "=f"(hi) : "l"(v));
    return make_float2(lo, hi);
}

// ---------------- device scratch ----------------
__device__ int   g_is64;
__device__ int   g_cnt[NN];
__device__ int   g_esrc[(size_t)NN * CAP];       // padded CSR: src per slot
__device__ float g_dinv[NN];
__device__ __align__(16) float g_h0[NN * HID];   // x @ conv0_w ; later reused as hB
__device__ __align__(16) float g_hA[NN * HID];   // agg layer-0 output (elu'd)
__device__ __align__(16) float g_t1[NN * HID];   // hA @ conv1_w
__device__ __align__(16) float g_p0[NN * NC];    // hA @ F0
__device__ __align__(16) float g_Wc[HID * 128];  // packed [conv1_w | F0 | 0]  (64x128)
__device__ __align__(16) float g_Wd[HID * 64];   // packed [F1 | 0]            (64x64)
__device__ float g_bf[NC];

__device__ __forceinline__ float elu1(float v) { return v > 0.0f ? v : expm1f(v); }

__device__ __forceinline__ int edge_at(const int* __restrict__ ei32, long long idx) {
    return g_is64 ? ei32[idx * 2] : ei32[idx];
}

// ---------------- zero counters + dtype detect (block 0) ----------------
__global__ void k_zero(const int* __restrict__ ei32) {
    int i = blockIdx.x * blockDim.x + threadIdx.x;
    if (i < NN) g_cnt[i] = 0;
    if (blockIdx.x == 0) {
        __shared__ int nz;
        if (threadIdx.x == 0) nz = 0;
        __syncthreads();
        if (ei32[threadIdx.x * 2 + 1] != 0) atomicAdd(&nz, 1);
        __syncthreads();
        if (threadIdx.x == 0) g_is64 = (nz == 0) ? 1 : 0;
    }
}

// ---------------- single-pass fill: slot = atomic cursor on g_cnt ----------------
__global__ void k_fill(const int* __restrict__ ei32) {
    int e = blockIdx.x * blockDim.x + threadIdx.x;
    if (e < EE) {
        int s = edge_at(ei32, e);
        int d = edge_at(ei32, (long long)EE + e);
        if (s >= 0 && s < NN && d >= 0 && d < NN) {
            int c = atomicAdd(&g_cnt[d], 1);
            if (c < CAP) g_esrc[(size_t)d * CAP + c] = s;
        }
    }
}

// ---------------- fold weights (blocks covering [0,WN)) + dinv (rest) ----------------
__global__ __launch_bounds__(256) void k_fusew(
        const float* __restrict__ lin0_w, const float* __restrict__ lin0_b,
        const float* __restrict__ lin1_w, const float* __restrict__ lin1_b,
        const float* __restrict__ out_w,  const float* __restrict__ out_b,
        const float* __restrict__ conv1_w) {
    int i = blockIdx.x * blockDim.x + threadIdx.x;

    if (blockIdx.x * 256 >= WN) {        // pure-dinv block: no staging
        int node = i - WN;
        if (node < NN) g_dinv[node] = rsqrtf((float)g_cnt[node] + 1.0f);
        return;
    }

    __shared__ float ow[2 * HID * NC];   // full out_w staged (20KB)
    for (int t = threadIdx.x; t < 2 * HID * NC; t += 256) ow[t] = out_w[t];
    __syncthreads();

    if (i < HID * 128) {                         // g_Wc
        int k = i >> 7, cc = i & 127;
        float v = 0.0f;
        if (cc < 64) {
            v = conv1_w[k * HID + cc];
        } else if (cc < 104) {
            int c = cc - 64;
            float s = 0.0f;
            #pragma unroll 8
            for (int m = 0; m < HID; m++) s += __ldg(&lin0_w[k * HID + m]) * ow[m * NC + c];
            v = s;
        }
        g_Wc[i] = v;
    } else if (i < HID * 128 + HID * 64) {       // g_Wd
        int jj = i - HID * 128;
        int k = jj >> 6, cc = jj & 63;
        float v = 0.0f;
        if (cc < NC) {
            float s = 0.0f;
            #pragma unroll 8
            for (int m = 0; m < HID; m++) s += __ldg(&lin1_w[k * HID + m]) * ow[(HID + m) * NC + cc];
            v = s;
        }
        g_Wd[jj] = v;
    } else if (i < WN) {                         // g_bf
        int c = i - HID * 128 - HID * 64;
        float s = out_b[c];
        for (int m = 0; m < HID; m++)
            s += lin0_b[m] * ow[m * NC + c] + lin1_b[m] * ow[(HID + m) * NC + c];
        g_bf[c] = s;
    } else {                                     // straddle block tail: dinv
        int node = i - WN;
        if (node < NN) g_dinv[node] = rsqrtf((float)g_cnt[node] + 1.0f);
    }
}

// ---------------- GEMM0 (R12 form): h0 = x @ conv0_w   BM128 BN64 BK32, f32x2, x-prefetch ----------------
__global__ __launch_bounds__(256) void k_gemm0(const float* __restrict__ x,
                                               const float* __restrict__ w) {
    __shared__ float As[32][132];   // k-major
    __shared__ float Ws[32][64];
    const int tid = threadIdx.x;
    const int row0 = blockIdx.x * 128;
    const int tx = tid & 15, ty = tid >> 4;
    const int lrow = tid & 127, lkc = tid >> 7;
    const int row = row0 + lrow;
    u64 acc2[4][4] = {};

    float4 pre[4];
    #pragma unroll
    for (int p = 0; p < 4; p++) {
        int kk = lkc * 16 + p * 4;
        pre[p] = (row < NN) ? *(const float4*)&x[(size_t)row * FIN + kk]
                            : make_float4(0, 0, 0, 0);
    }

    #pragma unroll
    for (int t = 0; t < 4; t++) {
        const int k0 = t * 32;
        #pragma unroll
        for (int p = 0; p < 4; p++) {
            int kk = lkc * 16 + p * 4;
            As[kk + 0][lrow] = pre[p].x; As[kk + 1][lrow] = pre[p].y;
            As[kk + 2][lrow] = pre[p].z; As[kk + 3][lrow] = pre[p].w;
        }
        #pragma unroll
        for (int r = 0; r < 2; r++) {
            int fi = tid + r * 256;
            int k = fi >> 4, c4 = (fi & 15) * 4;
            *(float4*)&Ws[k][c4] = *(const float4*)&w[(k0 + k) * HID + c4];
        }
        __syncthreads();
        if (t < 3) {
            #pragma unroll
            for (int p = 0; p < 4; p++) {
                int kk = (t + 1) * 32 + lkc * 16 + p * 4;
                pre[p] = (row < NN) ? *(const float4*)&x[(size_t)row * FIN + kk]
                                    : make_float4(0, 0, 0, 0);
            }
        }
        #pragma unroll
        for (int k = 0; k < 32; k++) {
            union { float4 f4; u64 d[2]; } ua0, ua1;
            ua0.f4 = *(const float4*)&As[k][ty * 8];
            ua1.f4 = *(const float4*)&As[k][ty * 8 + 4];
            u64 a0 = ua0.d[0], a1 = ua0.d[1], a2 = ua1.d[0], a3 = ua1.d[1];
            float4 b = *(const float4*)&Ws[k][tx * 4];
            u64 b0 = dup2(b.x), b1 = dup2(b.y), b2 = dup2(b.z), b3 = dup2(b.w);
            acc2[0][0] = fma2(a0, b0, acc2[0][0]); acc2[0][1] = fma2(a0, b1, acc2[0][1]);
            acc2[0][2] = fma2(a0, b2, acc2[0][2]); acc2[0][3] = fma2(a0, b3, acc2[0][3]);
            acc2[1][0] = fma2(a1, b0, acc2[1][0]); acc2[1][1] = fma2(a1, b1, acc2[1][1]);
            acc2[1][2] = fma2(a1, b2, acc2[1][2]); acc2[1][3] = fma2(a1, b3, acc2[1][3]);
            acc2[2][0] = fma2(a2, b0, acc2[2][0]); acc2[2][1] = fma2(a2, b1, acc2[2][1]);
            acc2[2][2] = fma2(a2, b2, acc2[2][2]); acc2[2][3] = fma2(a2, b3, acc2[2][3]);
            acc2[3][0] = fma2(a3, b0, acc2[3][0]); acc2[3][1] = fma2(a3, b1, acc2[3][1]);
            acc2[3][2] = fma2(a3, b2, acc2[3][2]); acc2[3][3] = fma2(a3, b3, acc2[3][3]);
        }
        __syncthreads();
    }
    #pragma unroll
    for (int i = 0; i < 4; i++) {
        float2 c0 = upk2(acc2[i][0]), c1 = upk2(acc2[i][1]);
        float2 c2 = upk2(acc2[i][2]), c3 = upk2(acc2[i][3]);
        int orow = row0 + ty * 8 + 2 * i;
        if (orow < NN)
            *(float4*)&g_h0[(size_t)orow * HID + tx * 4] = make_float4(c0.x, c1.x, c2.x, c3.x);
        if (orow + 1 < NN)
            *(float4*)&g_h0[(size_t)(orow + 1) * HID + tx * 4] = make_float4(c0.y, c1.y, c2.y, c3.y);
    }
}

// ---------------- gather-aggregate: TWO nodes per warp, float4 lanes, serial walk ----------------
// halves warp-instruction count per edge (one LDG triple serves 2 nodes), same L2 bytes
__global__ __launch_bounds__(256) void k_agg(int layer, const float* __restrict__ bias) {
    const float4* feat = (layer == 0) ? (const float4*)g_h0 : (const float4*)g_t1;
    float4*       outh = (layer == 0) ? (float4*)g_hA      : (float4*)g_h0;
    int warp = threadIdx.x >> 5;
    int lane = threadIdx.x & 31;
    int half = lane >> 4;           // which of the 2 nodes
    int l16  = lane & 15;           // float4 slot within the 64-float row
    int node = blockIdx.x * 16 + warp * 2 + half;
    bool valid = node < NN;

    int cnt = 0;
    float dd = 0.0f;
    if (valid) {
        cnt = g_cnt[node];
        if (cnt > CAP) cnt = CAP;
        dd = g_dinv[node];
    }
    const int* el = &g_esrc[(size_t)(valid ? node : 0) * CAP];
    int cntmax = cnt;
    {
        int other = __shfl_xor_sync(0xffffffffu, cnt, 16);
        if (other > cntmax) cntmax = other;
    }

    float4 acc = make_float4(0.0f, 0.0f, 0.0f, 0.0f);
    #pragma unroll 4
    for (int j = 0; j < cntmax; j++) {
        if (j < cnt) {
            int s = __ldg(&el[j]);
            float c = dd * __ldg(&g_dinv[s]);
            float4 v = __ldg(&feat[(size_t)s * 16 + l16]);
            acc.x = fmaf(c, v.x, acc.x);
            acc.y = fmaf(c, v.y, acc.y);
            acc.z = fmaf(c, v.z, acc.z);
            acc.w = fmaf(c, v.w, acc.w);
        }
    }
    if (valid) {
        // self-loop
        float4 v = __ldg(&feat[(size_t)node * 16 + l16]);
        float c = dd * dd;
        acc.x = fmaf(c, v.x, acc.x);
        acc.y = fmaf(c, v.y, acc.y);
        acc.z = fmaf(c, v.z, acc.z);
        acc.w = fmaf(c, v.w, acc.w);
        float4 bb = __ldg(&((const float4*)bias)[l16]);
        outh[(size_t)node * 16 + l16] =
            make_float4(elu1(acc.x + bb.x), elu1(acc.y + bb.y),
                        elu1(acc.z + bb.z), elu1(acc.w + bb.w));
    }
}

// ---------------- post0 (R12 form): [t1|p0] = hA @ g_Wc   BM128 BN128 BK32, f32x2 ----------------
__global__ __launch_bounds__(256) void k_post0() {
    __shared__ float As[32][132];
    __shared__ float Ws[32][128];
    const int tid = threadIdx.x;
    const int row0 = blockIdx.x * 128;
    const int tx = tid & 15, ty = tid >> 4;
    const int lrow = tid & 127, lkc = tid >> 7;
    u64 accL[4][4] = {}, accR[4][4] = {};

    for (int k0 = 0; k0 < HID; k0 += 32) {
        #pragma unroll
        for (int p = 0; p < 4; p++) {
            int kk = lkc * 16 + p * 4;
            int row = row0 + lrow;
            float4 v = (row < NN) ? *(const float4*)&g_hA[(size_t)row * HID + k0 + kk]
                                  : make_float4(0, 0, 0, 0);
            As[kk + 0][lrow] = v.x; As[kk + 1][lrow] = v.y;
            As[kk + 2][lrow] = v.z; As[kk + 3][lrow] = v.w;
        }
        #pragma unroll
        for (int r = 0; r < 4; r++) {
            int fi = tid + r * 256;
            int k = fi >> 5, c4 = (fi & 31) * 4;
            *(float4*)&Ws[k][c4] = *(const float4*)&g_Wc[(k0 + k) * 128 + c4];
        }
        __syncthreads();
        #pragma unroll
        for (int k = 0; k < 32; k++) {
            union { float4 f4; u64 d[2]; } ua0, ua1;
            ua0.f4 = *(const float4*)&As[k][ty * 8];
            ua1.f4 = *(const float4*)&As[k][ty * 8 + 4];
            u64 a0 = ua0.d[0], a1 = ua0.d[1], a2 = ua1.d[0], a3 = ua1.d[1];
            float4 bl = *(const float4*)&Ws[k][tx * 4];
            float4 br = *(const float4*)&Ws[k][64 + tx * 4];
            u64 l0 = dup2(bl.x), l1 = dup2(bl.y), l2 = dup2(bl.z), l3 = dup2(bl.w);
            u64 r0 = dup2(br.x), r1 = dup2(br.y), r2 = dup2(br.z), r3 = dup2(br.w);
            accL[0][0] = fma2(a0, l0, accL[0][0]); accL[0][1] = fma2(a0, l1, accL[0][1]);
            accL[0][2] = fma2(a0, l2, accL[0][2]); accL[0][3] = fma2(a0, l3, accL[0][3]);
            accL[1][0] = fma2(a1, l0, accL[1][0]); accL[1][1] = fma2(a1, l1, accL[1][1]);
            accL[1][2] = fma2(a1, l2, accL[1][2]); accL[1][3] = fma2(a1, l3, accL[1][3]);
            accL[2][0] = fma2(a2, l0, accL[2][0]); accL[2][1] = fma2(a2, l1, accL[2][1]);
            accL[2][2] = fma2(a2, l2, accL[2][2]); accL[2][3] = fma2(a2, l3, accL[2][3]);
            accL[3][0] = fma2(a3, l0, accL[3][0]); accL[3][1] = fma2(a3, l1, accL[3][1]);
            accL[3][2] = fma2(a3, l2, accL[3][2]); accL[3][3] = fma2(a3, l3, accL[3][3]);
            accR[0][0] = fma2(a0, r0, accR[0][0]); accR[0][1] = fma2(a0, r1, accR[0][1]);
            accR[0][2] = fma2(a0, r2, accR[0][2]); accR[0][3] = fma2(a0, r3, accR[0][3]);
            accR[1][0] = fma2(a1, r0, accR[1][0]); accR[1][1] = fma2(a1, r1, accR[1][1]);
            accR[1][2] = fma2(a1, r2, accR[1][2]); accR[1][3] = fma2(a1, r3, accR[1][3]);
            accR[2][0] = fma2(a2, r0, accR[2][0]); accR[2][1] = fma2(a2, r1, accR[2][1]);
            accR[2][2] = fma2(a2, r2, accR[2][2]); accR[2][3] = fma2(a2, r3, accR[2][3]);
            accR[3][0] = fma2(a3, r0, accR[3][0]); accR[3][1] = fma2(a3, r1, accR[3][1]);
            accR[3][2] = fma2(a3, r2, accR[3][2]); accR[3][3] = fma2(a3, r3, accR[3][3]);
        }
        __syncthreads();
    }
    #pragma unroll
    for (int i = 0; i < 4; i++) {
        float2 l0 = upk2(accL[i][0]), l1 = upk2(accL[i][1]);
        float2 l2 = upk2(accL[i][2]), l3 = upk2(accL[i][3]);
        float2 r0 = upk2(accR[i][0]), r1 = upk2(accR[i][1]);
        float2 r2 = upk2(accR[i][2]), r3 = upk2(accR[i][3]);
        int row = row0 + ty * 8 + 2 * i;
        if (row < NN) {
            *(float4*)&g_t1[(size_t)row * HID + tx * 4] = make_float4(l0.x, l1.x, l2.x, l3.x);
            if (tx < 10)
                *(float4*)&g_p0[(size_t)row * NC + tx * 4] = make_float4(r0.x, r1.x, r2.x, r3.x);
        }
        if (row + 1 < NN) {
            *(float4*)&g_t1[(size_t)(row + 1) * HID + tx * 4] = make_float4(l0.y, l1.y, l2.y, l3.y);
            if (tx < 10)
                *(float4*)&g_p0[(size_t)(row + 1) * NC + tx * 4] = make_float4(r0.y, r1.y, r2.y, r3.y);
        }
    }
}

// ---------------- post1 (R12 form): out = p0 + hB @ g_Wd + bf   BM128 BN64 BK32, f32x2 ----------------
__global__ __launch_bounds__(256) void k_post1(float* __restrict__ out) {
    __shared__ float As[32][132];
    __shared__ float Ws[32][64];
    const int tid = threadIdx.x;
    const int row0 = blockIdx.x * 128;
    const int tx = tid & 15, ty = tid >> 4;
    const int lrow = tid & 127, lkc = tid >> 7;
    u64 acc2[4][4] = {};

    for (int k0 = 0; k0 < HID; k0 += 32) {
        #pragma unroll
        for (int p = 0; p < 4; p++) {
            int kk = lkc * 16 + p * 4;
            int row = row0 + lrow;
            float4 v = (row < NN) ? *(const float4*)&g_h0[(size_t)row * HID + k0 + kk]
                                  : make_float4(0, 0, 0, 0);
            As[kk + 0][lrow] = v.x; As[kk + 1][lrow] = v.y;
            As[kk + 2][lrow] = v.z; As[kk + 3][lrow] = v.w;
        }
        #pragma unroll
        for (int r = 0; r < 2; r++) {
            int fi = tid + r * 256;
            int k = fi >> 4, c4 = (fi & 15) * 4;
            *(float4*)&Ws[k][c4] = *(const float4*)&g_Wd[(k0 + k) * 64 + c4];
        }
        __syncthreads();
        #pragma unroll
        for (int k = 0; k < 32; k++) {
            union { float4 f4; u64 d[2]; } ua0, ua1;
            ua0.f4 = *(const float4*)&As[k][ty * 8];
            ua1.f4 = *(const float4*)&As[k][ty * 8 + 4];
            u64 a0 = ua0.d[0], a1 = ua0.d[1], a2 = ua1.d[0], a3 = ua1.d[1];
            float4 b = *(const float4*)&Ws[k][tx * 4];
            u64 b0 = dup2(b.x), b1 = dup2(b.y), b2 = dup2(b.z), b3 = dup2(b.w);
            acc2[0][0] = fma2(a0, b0, acc2[0][0]); acc2[0][1] = fma2(a0, b1, acc2[0][1]);
            acc2[0][2] = fma2(a0, b2, acc2[0][2]); acc2[0][3] = fma2(a0, b3, acc2[0][3]);
            acc2[1][0] = fma2(a1, b0, acc2[1][0]); acc2[1][1] = fma2(a1, b1, acc2[1][1]);
            acc2[1][2] = fma2(a1, b2, acc2[1][2]); acc2[1][3] = fma2(a1, b3, acc2[1][3]);
            acc2[2][0] = fma2(a2, b0, acc2[2][0]); acc2[2][1] = fma2(a2, b1, acc2[2][1]);
            acc2[2][2] = fma2(a2, b2, acc2[2][2]); acc2[2][3] = fma2(a2, b3, acc2[2][3]);
            acc2[3][0] = fma2(a3, b0, acc2[3][0]); acc2[3][1] = fma2(a3, b1, acc2[3][1]);
            acc2[3][2] = fma2(a3, b2, acc2[3][2]); acc2[3][3] = fma2(a3, b3, acc2[3][3]);
        }
        __syncthreads();
    }
    if (tx * 4 < NC) {
        #pragma unroll
        for (int i = 0; i < 4; i++) {
            float2 c0 = upk2(acc2[i][0]), c1 = upk2(acc2[i][1]);
            float2 c2 = upk2(acc2[i][2]), c3 = upk2(acc2[i][3]);
            int row = row0 + ty * 8 + 2 * i;
            int c = tx * 4;
            float4 bf = *(const float4*)&g_bf[c];
            if (row < NN) {
                float4 p = *(const float4*)&g_p0[(size_t)row * NC + c];
                *(float4*)&out[(size_t)row * NC + c] =
                    make_float4(c0.x + p.x + bf.x, c1.x + p.y + bf.y,
                                c2.x + p.z + bf.z, c3.x + p.w + bf.w);
            }
            if (row + 1 < NN) {
                float4 p = *(const float4*)&g_p0[(size_t)(row + 1) * NC + c];
                *(float4*)&out[(size_t)(row + 1) * NC + c] =
                    make_float4(c0.y + p.x + bf.x, c1.y + p.y + bf.y,
                                c2.y + p.z + bf.z, c3.y + p.w + bf.w);
            }
        }
    }
}

// ---------------- launch (serial, R12 order) ----------------
extern "C" void kernel_launch(void* const* d_in, const int* in_sizes, int n_in,
                              void* d_out, int out_size) {
    const float* x       = (const float*)d_in[0];
    const int*   ei32    = (const int*)d_in[1];
    const float* conv0_w = (const float*)d_in[2];
    const float* conv0_b = (const float*)d_in[3];
    const float* lin0_w  = (const float*)d_in[4];
    const float* lin0_b  = (const float*)d_in[5];
    const float* conv1_w = (const float*)d_in[6];
    const float* conv1_b = (const float*)d_in[7];
    const float* lin1_w  = (const float*)d_in[8];
    const float* lin1_b  = (const float*)d_in[9];
    const float* out_w   = (const float*)d_in[10];
    const float* out_b   = (const float*)d_in[11];
    float* out = (float*)d_out;

    k_zero<<<NB1, 256>>>(ei32);
    k_fill<<<(EE + 255) / 256, 256>>>(ei32);
    k_fusew<<<(WN + NN + 255) / 256, 256>>>(
        lin0_w, lin0_b, lin1_w, lin1_b, out_w, out_b, conv1_w);
    k_gemm0<<<(NN + 127) / 128, 256>>>(x, conv0_w);

    k_agg<<<(NN + 15) / 16, 256>>>(0, conv0_b);
    k_post0<<<(NN + 127) / 128, 256>>>();
    k_agg<<<(NN + 15) / 16, 256>>>(1, conv1_b);
    k_post1<<<(NN + 127) / 128, 256>>>(out);
}